// round 15
// baseline (speedup 1.0000x reference)
#include <cuda_runtime.h>

typedef unsigned int u32;

#define NB 256

// ---------------- scratch (device globals; no allocation allowed) ----------
__device__ float g_h [NB * 511 * 256];   // h (tf32-rounded) for every node
__device__ float g_c [NB * 511 * 256];   // c (full fp32) for every node
__device__ float g_wx[768 * 256];        // W_iou tf32-rounded
__device__ float g_wu[768 * 256];        // U_iou tf32-rounded
__device__ float g_wf[256 * 256];        // U_f_w tf32-rounded
__device__ float g_x2[NB * 544];

// ---------------- helpers --------------------------------------------------
__device__ __forceinline__ float sigf(float x)   { return 1.0f / (1.0f + __expf(-x)); }
__device__ __forceinline__ float tanh_f(float x) { return 2.0f / (1.0f + __expf(-2.0f * x)) - 1.0f; }
__device__ __forceinline__ float tf32rn(float x) {
    u32 r; asm("cvt.rn.tf32.f32 %0, %1;" : "=r"(r) : "f"(x));
    return __uint_as_float(r);
}
__device__ __forceinline__ u32 tf32bits(float x) {
    u32 r; asm("cvt.rn.tf32.f32 %0, %1;" : "=r"(r) : "f"(x));
    return r;
}
__device__ __forceinline__ u32 smaddr(const void* p) {
    u32 a;
    asm("{ .reg .u64 t; cvta.to.shared.u64 t, %1; cvt.u32.u64 %0, t; }" : "=r"(a) : "l"(p));
    return a;
}

#define CPA(dst, src) asm volatile("cp.async.cg.shared.global [%0], [%1], 16;" :: "r"(dst), "l"(src))
#define CPC()  asm volatile("cp.async.commit_group;" ::: "memory")
#define CPW(n) asm volatile("cp.async.wait_group %0;" :: "n"(n) : "memory")

// m16n8k8 tf32 MMA, D += A*B (D/C aliased)
__device__ __forceinline__ void mma8(float* d, const u32* a, const u32* b) {
    asm volatile("mma.sync.aligned.m16n8k8.row.col.f32.tf32.tf32.f32 "
        "{%0,%1,%2,%3}, {%4,%5,%6,%7}, {%8,%9}, {%0,%1,%2,%3};"
        : "+f"(d[0]), "+f"(d[1]), "+f"(d[2]), "+f"(d[3])
        : "r"(a[0]), "r"(a[1]), "r"(a[2]), "r"(a[3]), "r"(b[0]), "r"(b[1]));
}

// ---------------------------------------------------------------------------
// prep_round: round GEMM weights to tf32 (RN) into scratch (weights only now;
// X and h are rounded in-register at fragment-load time).
// ---------------------------------------------------------------------------
__global__ void prep_round(const float* __restrict__ Wiou,
                           const float* __restrict__ Uiou, const float* __restrict__ Ufw)
{
    const int W4 = 49152;
    int i = blockIdx.x * 256 + threadIdx.x;   // float4 index
    const float4* src; float* dst;
    if (i < W4) {
        int e = i * 4;
        src = (const float4*)(Wiou + e); dst = g_wx + e;
    } else if (i < 2 * W4) {
        int e = (i - W4) * 4;
        src = (const float4*)(Uiou + e); dst = g_wu + e;
    } else {
        int e = (i - 2 * W4) * 4;
        src = (const float4*)(Ufw + e); dst = g_wf + e;
    }
    float4 v = *src;
    v.x = tf32rn(v.x); v.y = tf32rn(v.y); v.z = tf32rn(v.z); v.w = tf32rn(v.w);
    *(float4*)dst = v;
}

// ---------------------------------------------------------------------------
// leaf_mma: iou = X_leaf @ W_iou^T via mma.sync tf32, fused LSTM epilogue.
// Block = 64 rows x 64 cols, 4 warps; warp (rh, chalf) owns a 32x32 tile of
// ALL 3 gates. X loaded raw, fragments rounded to tf32 in-register.
// ---------------------------------------------------------------------------
__global__ __launch_bounds__(128, 3)
void leaf_mma(const float* __restrict__ X, const float* __restrict__ bi,
              const float* __restrict__ Cin)
{
    extern __shared__ float dsm[];   // 2 x 8192 floats
    const int tid = threadIdx.x, wid = tid >> 5, lane = tid & 31;
    const int col0 = blockIdx.x * 64, r0 = blockIdx.y * 64;
    const int rh = wid >> 1, chalf = wid & 1;
    const int g8 = lane >> 2, j = lane & 3, cswz = g8 & 3;
    const u32 smb = smaddr(dsm);

    float acc[3][2][4][4];
#pragma unroll
    for (int g = 0; g < 3; ++g)
#pragma unroll
        for (int mf = 0; mf < 2; ++mf)
#pragma unroll
            for (int nf = 0; nf < 4; ++nf)
#pragma unroll
                for (int e = 0; e < 4; ++e) acc[g][mf][nf][e] = 0.0f;

    auto fill = [&](int c) {
        const u32 base = smb + (c & 1) * 32768;
#pragma unroll
        for (int it = 0; it < 4; ++it) {                 // A: 512 float4 (X rows)
            int i = tid + it * 128, r = i >> 3, q = i & 7;
            int rg = r0 + r, b = rg >> 8, jn = rg & 255;
            long grow = b * 511 + 255 + jn;
            CPA(base + r * 128 + ((q ^ (r & 3)) << 4),
                X + grow * 256 + c * 32 + q * 4);
        }
#pragma unroll
        for (int it = 0; it < 12; ++it) {                // B: 1536 float4
            int i = tid + it * 128, g = i >> 9, rem = i & 511, n = rem >> 3, q = rem & 7;
            CPA(base + 8192 + g * 8192 + n * 128 + ((q ^ (n & 3)) << 4),
                g_wx + (g * 256 + col0 + n) * 256 + c * 32 + q * 4);
        }
        CPC();
    };

    fill(0);
    fill(1);

#pragma unroll 1
    for (int c = 0; c < 8; ++c) {
        if (c == 7) { CPW(0); } else { CPW(1); }
        __syncthreads();
        const float* Ab = dsm + (c & 1) * 8192;
        const float* Bb = Ab + 2048;
#pragma unroll
        for (int s = 0; s < 4; ++s) {
            const int p0 = (((2 * s) ^ cswz) << 2) | j;
            const int p1 = (((2 * s + 1) ^ cswz) << 2) | j;
            u32 aa[2][4];
#pragma unroll
            for (int mf = 0; mf < 2; ++mf) {
                const int rr = (rh * 32 + mf * 16 + g8) * 32;
                aa[mf][0] = tf32bits(Ab[rr + p0]);
                aa[mf][1] = tf32bits(Ab[rr + 256 + p0]);
                aa[mf][2] = tf32bits(Ab[rr + p1]);
                aa[mf][3] = tf32bits(Ab[rr + 256 + p1]);
            }
#pragma unroll
            for (int g = 0; g < 3; ++g)
#pragma unroll
                for (int nf = 0; nf < 4; ++nf) {
                    const int nn = (g * 64 + chalf * 32 + nf * 8 + g8) * 32;
                    u32 bb[2] = { __float_as_uint(Bb[nn + p0]),
                                  __float_as_uint(Bb[nn + p1]) };
                    mma8(acc[g][0][nf], aa[0], bb);
                    mma8(acc[g][1][nf], aa[1], bb);
                }
        }
        __syncthreads();
        if (c < 6) fill(c + 2);
    }

    // ---- epilogue: gates + cell update + store h,c ----
#pragma unroll
    for (int mf = 0; mf < 2; ++mf)
#pragma unroll
    for (int e = 0; e < 2; ++e) {
        const int r  = r0 + rh * 32 + mf * 16 + g8 + e * 8;
        const int b  = r >> 8;
        const int jn = r & 255;
        const long grow = b * 511 + 255 + jn;
#pragma unroll
        for (int nf = 0; nf < 4; ++nf) {
            const int col = col0 + chalf * 32 + nf * 8 + j * 2;
            float2 ci = *(const float2*)(Cin + grow * 256 + col);
            float cv[2], hv[2];
#pragma unroll
            for (int q = 0; q < 2; ++q) {
                float I = sigf(acc[0][mf][nf][e * 2 + q] + bi[col + q]);
                float O = sigf(acc[1][mf][nf][e * 2 + q] + bi[256 + col + q]);
                float U = tanh_f(acc[2][mf][nf][e * 2 + q] + bi[512 + col + q]);
                float cc = fmaf(I, U, q ? ci.y : ci.x);
                cv[q] = cc;
                hv[q] = tf32rn(O * tanh_f(cc));
            }
            *(float2*)(g_c + grow * 256 + col) = make_float2(cv[0], cv[1]);
            *(float2*)(g_h + grow * 256 + col) = make_float2(hv[0], hv[1]);
        }
    }
}

// ---------------------------------------------------------------------------
// level_mma: FUSED fgate + iou for one tree level. 8 warps, 64 parents x 64
// cols per block. Warps 0-3 (iou): A-fragments built in-register as
// tf32rn(ch0+ch1) (MMA linearity, h_tild never materialized), gates i/o/u.
// Warps 4-7 (fgate): f0 = ch0@Uf, f1 = ch1@Uf from the same smem tiles.
// Epilogue: fgate warps form c_agg = F0*c0 + F1*c1 in smem (identical
// fragment mapping), iou warps finish c = i*u + c_agg, h = o*tanh(c).
// Smem chunk: A ch0+ch1 (16KB) + B Uf/Ui/Uo/Uu (32KB), double buffered.
// ---------------------------------------------------------------------------
__global__ __launch_bounds__(256, 1)
void level_mma(const float* __restrict__ bi, const float* __restrict__ bf,
               int m, int mshift)
{
    extern __shared__ float dsm[];   // 2 x 12288 floats (96KB)
    const int tid = threadIdx.x, wid = tid >> 5, lane = tid & 31;
    const int gc0 = blockIdx.x * 64, r0 = blockIdx.y * 64;
    const int grp = wid >> 2, w4 = wid & 3;
    const int rh = w4 >> 1, chalf = w4 & 1;
    const int g8 = lane >> 2, j = lane & 3, cswz = g8 & 3;
    const u32 smb = smaddr(dsm);

    float acc[3][2][4][4];    // grp0: i/o/u   grp1: [0]=f0,[1]=f1 ([2] unused)
#pragma unroll
    for (int g = 0; g < 3; ++g)
#pragma unroll
        for (int mf = 0; mf < 2; ++mf)
#pragma unroll
            for (int nf = 0; nf < 4; ++nf)
#pragma unroll
                for (int e = 0; e < 4; ++e) acc[g][mf][nf][e] = 0.0f;

    auto fill = [&](int c) {
        const u32 base = smb + (c & 1) * 49152;
#pragma unroll
        for (int it = 0; it < 4; ++it) {                 // A: 1024 float4 (2 children)
            int i = tid + it * 256, ch = i >> 9, rem = i & 511, r = rem >> 3, q = rem & 7;
            int rg = r0 + r, b = rg >> mshift, jn = rg & (m - 1);
            long cg = b * 511 + 2 * m - 1 + 2 * jn + ch;
            CPA(base + ch * 8192 + r * 128 + ((q ^ (r & 3)) << 4),
                g_h + cg * 256 + c * 32 + q * 4);
        }
#pragma unroll
        for (int it = 0; it < 8; ++it) {                 // B: 2048 float4 (Uf,Ui,Uo,Uu)
            int i = tid + it * 256, t = i >> 9, rem = i & 511, n = rem >> 3, q = rem & 7;
            const float* src = (t == 0)
                ? g_wf + (gc0 + n) * 256 + c * 32 + q * 4
                : g_wu + ((t - 1) * 256 + gc0 + n) * 256 + c * 32 + q * 4;
            CPA(base + 16384 + t * 8192 + n * 128 + ((q ^ (n & 3)) << 4), src);
        }
        CPC();
    };

    fill(0);
    fill(1);

#pragma unroll 1
    for (int c = 0; c < 8; ++c) {
        if (c == 7) { CPW(0); } else { CPW(1); }
        __syncthreads();
        const float* A0 = dsm + (c & 1) * 12288;
        const float* A1 = A0 + 2048;
        const float* Bf = A0 + 4096;        // Uf tile
#pragma unroll
        for (int s = 0; s < 4; ++s) {
            const int p0 = (((2 * s) ^ cswz) << 2) | j;
            const int p1 = (((2 * s + 1) ^ cswz) << 2) | j;
            if (grp == 0) {
                // iou: A = tf32rn(ch0 + ch1)
                u32 aa[2][4];
#pragma unroll
                for (int mf = 0; mf < 2; ++mf) {
                    const int rr = (rh * 32 + mf * 16 + g8) * 32;
                    aa[mf][0] = tf32bits(A0[rr + p0]       + A1[rr + p0]);
                    aa[mf][1] = tf32bits(A0[rr + 256 + p0] + A1[rr + 256 + p0]);
                    aa[mf][2] = tf32bits(A0[rr + p1]       + A1[rr + p1]);
                    aa[mf][3] = tf32bits(A0[rr + 256 + p1] + A1[rr + 256 + p1]);
                }
#pragma unroll
                for (int g = 0; g < 3; ++g)
#pragma unroll
                    for (int nf = 0; nf < 4; ++nf) {
                        const float* Bg = Bf + (g + 1) * 2048;
                        const int nn = (chalf * 32 + nf * 8 + g8) * 32;
                        u32 bb[2] = { __float_as_uint(Bg[nn + p0]),
                                      __float_as_uint(Bg[nn + p1]) };
                        mma8(acc[g][0][nf], aa[0], bb);
                        mma8(acc[g][1][nf], aa[1], bb);
                    }
            } else {
                // fgate: f0 from ch0, f1 from ch1 (already tf32-rounded)
                u32 a0[2][4], a1[2][4];
#pragma unroll
                for (int mf = 0; mf < 2; ++mf) {
                    const int rr = (rh * 32 + mf * 16 + g8) * 32;
                    a0[mf][0] = __float_as_uint(A0[rr + p0]);
                    a0[mf][1] = __float_as_uint(A0[rr + 256 + p0]);
                    a0[mf][2] = __float_as_uint(A0[rr + p1]);
                    a0[mf][3] = __float_as_uint(A0[rr + 256 + p1]);
                    a1[mf][0] = __float_as_uint(A1[rr + p0]);
                    a1[mf][1] = __float_as_uint(A1[rr + 256 + p0]);
                    a1[mf][2] = __float_as_uint(A1[rr + p1]);
                    a1[mf][3] = __float_as_uint(A1[rr + 256 + p1]);
                }
#pragma unroll
                for (int nf = 0; nf < 4; ++nf) {
                    const int nn = (chalf * 32 + nf * 8 + g8) * 32;
                    u32 bb[2] = { __float_as_uint(Bf[nn + p0]),
                                  __float_as_uint(Bf[nn + p1]) };
                    mma8(acc[0][0][nf], a0[0], bb);
                    mma8(acc[0][1][nf], a0[1], bb);
                    mma8(acc[1][0][nf], a1[0], bb);
                    mma8(acc[1][1][nf], a1[1], bb);
                }
            }
        }
        __syncthreads();
        if (c < 6) fill(c + 2);
    }

    // ---- epilogue phase 1: fgate warps -> c_agg in smem (stride 66) ----
    float* cagg = dsm;
    if (grp == 1) {
#pragma unroll
        for (int mf = 0; mf < 2; ++mf)
#pragma unroll
        for (int e = 0; e < 2; ++e) {
            const int rl = rh * 32 + mf * 16 + g8 + e * 8;
            const int r  = r0 + rl;
            const int b  = r >> mshift;
            const int jn = r & (m - 1);
            const long cg = (long)(b * 511 + 2 * m - 1 + 2 * jn) * 256;
#pragma unroll
            for (int nf = 0; nf < 4; ++nf) {
                const int cl  = chalf * 32 + nf * 8 + j * 2;
                const int col = gc0 + cl;
                float2 c0v = *(const float2*)(g_c + cg + col);
                float2 c1v = *(const float2*)(g_c + cg + 256 + col);
                float b0 = bf[col], b1 = bf[col + 1];
                float F00 = sigf(acc[0][mf][nf][e * 2 + 0] + b0);
                float F01 = sigf(acc[0][mf][nf][e * 2 + 1] + b1);
                float F10 = sigf(acc[1][mf][nf][e * 2 + 0] + b0);
                float F11 = sigf(acc[1][mf][nf][e * 2 + 1] + b1);
                *(float2*)&cagg[rl * 66 + cl] =
                    make_float2(F00 * c0v.x + F10 * c1v.x, F01 * c0v.y + F11 * c1v.y);
            }
        }
    }
    __syncthreads();

    // ---- epilogue phase 2: iou warps -> cell update, store h,c ----
    if (grp == 0) {
#pragma unroll
        for (int mf = 0; mf < 2; ++mf)
#pragma unroll
        for (int e = 0; e < 2; ++e) {
            const int rl = rh * 32 + mf * 16 + g8 + e * 8;
            const int r  = r0 + rl;
            const int b  = r >> mshift;
            const int jn = r & (m - 1);
            const long grow = b * 511 + (m - 1) + jn;
#pragma unroll
            for (int nf = 0; nf < 4; ++nf) {
                const int cl  = chalf * 32 + nf * 8 + j * 2;
                const int col = gc0 + cl;
                float2 ca = *(const float2*)&cagg[rl * 66 + cl];
                float cv[2], hv[2];
#pragma unroll
                for (int q = 0; q < 2; ++q) {
                    float I = sigf(acc[0][mf][nf][e * 2 + q] + bi[col + q]);
                    float O = sigf(acc[1][mf][nf][e * 2 + q] + bi[256 + col + q]);
                    float U = tanh_f(acc[2][mf][nf][e * 2 + q] + bi[512 + col + q]);
                    float cc = fmaf(I, U, q ? ca.y : ca.x);
                    cv[q] = cc;
                    hv[q] = tf32rn(O * tanh_f(cc));
                }
                *(float2*)(g_c + grow * 256 + col) = make_float2(cv[0], cv[1]);
                *(float2*)(g_h + grow * 256 + col) = make_float2(hv[0], hv[1]);
            }
        }
    }
}

// ---------------------------------------------------------------------------
// build_x2: x2[b] = [ h(node0) | mean over nodes 1..509 of h | emo[b] ]
// ---------------------------------------------------------------------------
__global__ void build_x2(const float* __restrict__ emo)
{
    const int idx = blockIdx.x * 256 + threadIdx.x;
    const int b   = idx / 544;
    const int c2  = idx - b * 544;
    float v;
    if (c2 < 256) {
        v = g_h[(long)b * 511 * 256 + c2];
    } else if (c2 < 512) {
        const int hc = c2 - 256;
        const float* p = g_h + (long)b * 511 * 256 + 256 + hc;  // node 1
        float s0 = 0.f, s1 = 0.f, s2 = 0.f, s3 = 0.f;
        int nd = 0;
        for (; nd < 508; nd += 4) {
            s0 += p[(nd + 0) * 256];
            s1 += p[(nd + 1) * 256];
            s2 += p[(nd + 2) * 256];
            s3 += p[(nd + 3) * 256];
        }
        s0 += p[508 * 256];  // node 509
        v = (s0 + s1 + s2 + s3) * (1.0f / 509.0f);
    } else {
        v = emo[b * 32 + (c2 - 512)];
    }
    g_x2[idx] = v;
}

// ---------------------------------------------------------------------------
// mlp_kernel: one block per batch row; 544->128 relu, 128->64 relu, 64->4 sig
// ---------------------------------------------------------------------------
__global__ __launch_bounds__(128)
void mlp_kernel(const float* __restrict__ W_in, const float* __restrict__ b_in,
                const float* __restrict__ W_mid, const float* __restrict__ b_mid,
                const float* __restrict__ W_out, const float* __restrict__ b_out,
                float* __restrict__ out)
{
    __shared__ __align__(16) float xs[544];
    __shared__ __align__(16) float y0[128];
    __shared__ __align__(16) float y1[64];
    const int b = blockIdx.x;
    const int t = threadIdx.x;

    for (int i = t; i < 544; i += 128) xs[i] = g_x2[b * 544 + i];
    __syncthreads();

    {
        float acc = b_in[t];
        const float4* w = (const float4*)(W_in + t * 544);
        const float4* x = (const float4*)xs;
#pragma unroll 8
        for (int q = 0; q < 136; ++q) {
            float4 wv = w[q], xv = x[q];
            acc = fmaf(wv.x, xv.x, acc); acc = fmaf(wv.y, xv.y, acc);
            acc = fmaf(wv.z, xv.z, acc); acc = fmaf(wv.w, xv.w, acc);
        }
        y0[t] = fmaxf(acc, 0.0f);
    }
    __syncthreads();

    if (t < 64) {
        float acc = b_mid[t];
        const float4* w = (const float4*)(W_mid + t * 128);
        const float4* x = (const float4*)y0;
#pragma unroll
        for (int q = 0; q < 32; ++q) {
            float4 wv = w[q], xv = x[q];
            acc = fmaf(wv.x, xv.x, acc); acc = fmaf(wv.y, xv.y, acc);
            acc = fmaf(wv.z, xv.z, acc); acc = fmaf(wv.w, xv.w, acc);
        }
        y1[t] = fmaxf(acc, 0.0f);
    }
    __syncthreads();

    if (t < 4) {
        float acc = b_out[t];
        const float4* w = (const float4*)(W_out + t * 64);
        const float4* x = (const float4*)y1;
#pragma unroll
        for (int q = 0; q < 16; ++q) {
            float4 wv = w[q], xv = x[q];
            acc = fmaf(wv.x, xv.x, acc); acc = fmaf(wv.y, xv.y, acc);
            acc = fmaf(wv.z, xv.z, acc); acc = fmaf(wv.w, xv.w, acc);
        }
        out[b * 4 + t] = sigf(acc);
    }
}

// ---------------------------------------------------------------------------
extern "C" void kernel_launch(void* const* d_in, const int* in_sizes, int n_in,
                              void* d_out, int out_size)
{
    const float* X     = (const float*)d_in[0];
    // d_in[1] = h (zeros, never read by the reference)
    const float* c_in  = (const float*)d_in[2];
    const float* emo   = (const float*)d_in[3];
    const float* W_iou = (const float*)d_in[4];
    const float* U_iou = (const float*)d_in[5];
    const float* b_iou = (const float*)d_in[6];
    const float* U_f_w = (const float*)d_in[7];
    const float* U_f_b = (const float*)d_in[8];
    const float* W_in  = (const float*)d_in[9];
    const float* b_in  = (const float*)d_in[10];
    const float* W_mid = (const float*)d_in[11];
    const float* b_mid = (const float*)d_in[12];
    const float* W_out = (const float*)d_in[13];
    const float* b_out = (const float*)d_in[14];
    float* out = (float*)d_out;

    const int LEAF_SMEM  = 65536;   // 2 x (8KB A + 24KB B)
    const int LEVEL_SMEM = 98304;   // 2 x (16KB A + 32KB B)
    static int s_attr_done = 0;
    if (!s_attr_done) {
        cudaFuncSetAttribute(leaf_mma,  cudaFuncAttributeMaxDynamicSharedMemorySize, LEAF_SMEM);
        cudaFuncSetAttribute(level_mma, cudaFuncAttributeMaxDynamicSharedMemorySize, LEVEL_SMEM);
        s_attr_done = 1;
    }

    prep_round<<<448, 256>>>(W_iou, U_iou, U_f_w);

    // Leaf level: 65536 rows
    leaf_mma<<<dim3(4, 1024), 128, LEAF_SMEM>>>(X, b_iou, c_in);

    // Internal levels d = 7 .. 0 (fully fused fgate+iou per level)
    for (int d = 7; d >= 0; --d) {
        int m = 1 << d;
        level_mma<<<dim3(4, (NB * m) / 64), 256, LEVEL_SMEM>>>(b_iou, U_f_b, m, d);
    }

    build_x2<<<(NB * 544) / 256, 256>>>(emo);
    mlp_kernel<<<NB, 128>>>(W_in, b_in, W_mid, b_mid, W_out, b_out, out);
}